// round 13
// baseline (speedup 1.0000x reference)
#include <cuda_runtime.h>
#include <cuda_bf16.h>
#include <math_constants.h>

// VQ forward: z (B,256) f32, embed (512,256) f32.
// out = [ quantized (B*256) | codes (B, as float) | commit (1) ]  (float32)
//
// Numerics contract (validated R9, PASS):
//   dot:    single-accumulator fp32 fma chain, k ascending (per row,col)
//   z_sq/e_sq: XLA:GPU row-reduce (vec=2, 128 thr, shfl trees)
//   dist = (z_sq - (2.0f*dot)) + e_sq  (separately rounded)
//   argmin: strict <, ascending col, tie -> lower index
//   quantized = z + (q - z), separately rounded
//
// R12 = R9 structure (TM=64/TN=64, per-(ct,kt) staging, high occupancy)
// with a mov-free inner loop: lanes = row pairs (a via LDS.128 from k-major
// Z), E pre-duplicated (e,e) so b comes via 2x LDS.128. 11 instr / 16 FMA.

#define D_DIM 256
#define K_CODES 512
#define TM 64
#define TN 64
#define TK 16
#define NTHREADS 256
#define B_MAX 262144

__device__ float g_esq[K_CODES];
__device__ float g_zsq[B_MAX];
__device__ float g_partials[8192];

__device__ __forceinline__ void fma2(unsigned long long& d,
                                     unsigned long long a,
                                     unsigned long long b) {
    asm("fma.rn.f32x2 %0, %1, %2, %0;" : "+l"(d) : "l"(a), "l"(b));
}
__device__ __forceinline__ float2 upk2(unsigned long long v) {
    float2 f;
    asm("mov.b64 {%0, %1}, %2;" : "=f"(f.x), "=f"(f.y) : "l"(v));
    return f;
}

// XLA:GPU row-reduce replica for sum(x*x) over a 256-float row.
// dest==0 -> g_esq, dest==1 -> g_zsq (symbols touched in device code only)
__global__ void k_rowsq_xla(const float* __restrict__ x, int rows, int dest) {
    __shared__ float w[8];
    const unsigned full = 0xffffffffu;
    int grp = threadIdx.x >> 7;
    int t = threadIdx.x & 127;
    long row = (long)blockIdx.x * 2 + grp;

    float s = 0.f;
    if (row < rows) {
        const float2 v = *(const float2*)(x + row * D_DIM + 2 * t);
        s = __fadd_rn(__fmul_rn(v.x, v.x), __fmul_rn(v.y, v.y));
    }
    s = __fadd_rn(s, __shfl_down_sync(full, s, 16));
    s = __fadd_rn(s, __shfl_down_sync(full, s, 8));
    s = __fadd_rn(s, __shfl_down_sync(full, s, 4));
    s = __fadd_rn(s, __shfl_down_sync(full, s, 2));
    s = __fadd_rn(s, __shfl_down_sync(full, s, 1));
    if ((threadIdx.x & 31) == 0) w[threadIdx.x >> 5] = s;
    __syncthreads();
    if ((t >> 5) == 0) {
        int lane = t & 31;
        float v = (lane < 4) ? w[grp * 4 + lane] : 0.f;
        v = __fadd_rn(v, __shfl_down_sync(full, v, 16));
        v = __fadd_rn(v, __shfl_down_sync(full, v, 8));
        v = __fadd_rn(v, __shfl_down_sync(full, v, 4));
        v = __fadd_rn(v, __shfl_down_sync(full, v, 2));
        v = __fadd_rn(v, __shfl_down_sync(full, v, 1));
        if (lane == 0 && row < rows) {
            if (dest == 0) g_esq[row] = v;
            else           g_zsq[row] = v;
        }
    }
}

__global__ __launch_bounds__(NTHREADS)
void k_main(const float* __restrict__ z, const float* __restrict__ embed,
            float* __restrict__ out, int B, int write_codes) {
    __shared__ __align__(16) float  Zs[TK][TM];     // 4KB  k-major Z tile
    __shared__ __align__(16) float2 Ed[TK][TN];     // 8KB  duplicated E tile
    __shared__ float sMin[TM][16];                  // 4KB
    __shared__ int   sIdx[TM][16];                  // 4KB
    __shared__ int   sCode[TM];
    __shared__ float sPart[NTHREADS];
    __shared__ float sZsq[TM];

    const int tid = threadIdx.x;
    const int tx = tid & 15;          // cols tx*4 .. tx*4+3
    const int ty = tid >> 4;          // rows ty*4 .. ty*4+3 (2 f32x2 pairs)
    const long rowBase = (long)blockIdx.x * TM;

    if (tid < TM) sZsq[tid] = g_zsq[rowBase + tid];

    float rmin[4];
    int   ridx[4];
#pragma unroll
    for (int r = 0; r < 4; r++) { rmin[r] = CUDART_INF_F; ridx[r] = 0; }

    const int mLd = tid >> 2;         // 0..63 : row/code index for tile loads
    const int kq  = tid & 3;          // 0..3  : which float4 along k

    for (int ct = 0; ct < K_CODES / TN; ++ct) {
        unsigned long long acc[2][4];   // [rowpair][col]
#pragma unroll
        for (int p = 0; p < 2; p++)
#pragma unroll
            for (int c = 0; c < 4; c++) acc[p][c] = 0ull;

        for (int kt = 0; kt < D_DIM / TK; ++kt) {
            // ---- stage tiles (transposed into [k][m]) ----
            float4 zv = *(const float4*)(z + (rowBase + mLd) * D_DIM + kt * TK + kq * 4);
            Zs[kq * 4 + 0][mLd] = zv.x;
            Zs[kq * 4 + 1][mLd] = zv.y;
            Zs[kq * 4 + 2][mLd] = zv.z;
            Zs[kq * 4 + 3][mLd] = zv.w;
            float4 ev = *(const float4*)(embed + (long)(ct * TN + mLd) * D_DIM + kt * TK + kq * 4);
            Ed[kq * 4 + 0][mLd] = make_float2(ev.x, ev.x);
            Ed[kq * 4 + 1][mLd] = make_float2(ev.y, ev.y);
            Ed[kq * 4 + 2][mLd] = make_float2(ev.z, ev.z);
            Ed[kq * 4 + 3][mLd] = make_float2(ev.w, ev.w);
            __syncthreads();

            // ---- 16 k-steps: 1 LDS.128 (a pairs) + 2 LDS.128 (b dup)
            //      + 8 FFMA2, zero movs ----
#pragma unroll
            for (int k = 0; k < TK; k++) {
                ulonglong2 a = *(const ulonglong2*)&Zs[k][ty * 4];
                ulonglong2 b01 = *(const ulonglong2*)&Ed[k][tx * 4];
                ulonglong2 b23 = *(const ulonglong2*)&Ed[k][tx * 4 + 2];
                fma2(acc[0][0], a.x, b01.x); fma2(acc[0][1], a.x, b01.y);
                fma2(acc[0][2], a.x, b23.x); fma2(acc[0][3], a.x, b23.y);
                fma2(acc[1][0], a.y, b01.x); fma2(acc[1][1], a.y, b01.y);
                fma2(acc[1][2], a.y, b23.x); fma2(acc[1][3], a.y, b23.y);
            }
            __syncthreads();
        }

        // ---- dist = (z_sq - (2*dot)) + e_sq; running argmin, cols asc ----
        int cb = ct * TN + tx * 4;
#pragma unroll
        for (int c = 0; c < 4; c++) {
            int col = cb + c;
            float eq = g_esq[col];
            float2 d0 = upk2(acc[0][c]);
            float2 d1 = upk2(acc[1][c]);
            float s0 = __fadd_rn(__fsub_rn(sZsq[ty * 4 + 0], __fmul_rn(2.0f, d0.x)), eq);
            float s1 = __fadd_rn(__fsub_rn(sZsq[ty * 4 + 1], __fmul_rn(2.0f, d0.y)), eq);
            float s2 = __fadd_rn(__fsub_rn(sZsq[ty * 4 + 2], __fmul_rn(2.0f, d1.x)), eq);
            float s3 = __fadd_rn(__fsub_rn(sZsq[ty * 4 + 3], __fmul_rn(2.0f, d1.y)), eq);
            if (s0 < rmin[0]) { rmin[0] = s0; ridx[0] = col; }
            if (s1 < rmin[1]) { rmin[1] = s1; ridx[1] = col; }
            if (s2 < rmin[2]) { rmin[2] = s2; ridx[2] = col; }
            if (s3 < rmin[3]) { rmin[3] = s3; ridx[3] = col; }
        }
    }

    // ---- cross-thread argmin reduce (lower index wins ties) ----
#pragma unroll
    for (int r = 0; r < 4; r++) {
        sMin[ty * 4 + r][tx] = rmin[r];
        sIdx[ty * 4 + r][tx] = ridx[r];
    }
    __syncthreads();
    if (tid < TM) {
        float m = sMin[tid][0];
        int ix = sIdx[tid][0];
#pragma unroll
        for (int x = 1; x < 16; x++) {
            float v = sMin[tid][x];
            int i2 = sIdx[tid][x];
            if (v < m || (v == m && i2 < ix)) { m = v; ix = i2; }
        }
        sCode[tid] = ix;
        if (write_codes)
            out[(long)B * D_DIM + rowBase + tid] = (float)ix;
    }
    __syncthreads();

    // ---- epilogue: gather q, quantized = z + (q - z), commit partial ----
    float lsum = 0.f;
    const float4* z4 = (const float4*)z;
    const float4* e4 = (const float4*)embed;
    float4* o4 = (float4*)out;
#pragma unroll 4
    for (int i = tid; i < TM * (D_DIM / 4); i += NTHREADS) {
        int r = i >> 6;
        int c = i & 63;
        int code = sCode[r];
        float4 qv = __ldg(&e4[(long)code * (D_DIM / 4) + c]);
        float4 zv = z4[(rowBase + r) * (D_DIM / 4) + c];
        float dx = __fsub_rn(qv.x, zv.x);
        float dy = __fsub_rn(qv.y, zv.y);
        float dz = __fsub_rn(qv.z, zv.z);
        float dw = __fsub_rn(qv.w, zv.w);
        float4 ov;
        ov.x = __fadd_rn(zv.x, dx);
        ov.y = __fadd_rn(zv.y, dy);
        ov.z = __fadd_rn(zv.z, dz);
        ov.w = __fadd_rn(zv.w, dw);
        o4[(rowBase + r) * (D_DIM / 4) + c] = ov;
        lsum += dx * dx + dy * dy + dz * dz + dw * dw;
    }
    sPart[tid] = lsum;
    __syncthreads();
#pragma unroll
    for (int s = NTHREADS / 2; s > 0; s >>= 1) {
        if (tid < s) sPart[tid] += sPart[tid + s];
        __syncthreads();
    }
    if (tid == 0) g_partials[blockIdx.x] = sPart[0];
}

__global__ void k_fin(float* __restrict__ out, int nblk, long BD, long B) {
    __shared__ double sp[256];
    int tid = threadIdx.x;
    double s = 0.0;
    for (int i = tid; i < nblk; i += 256) s += (double)g_partials[i];
    sp[tid] = s;
    __syncthreads();
    for (int st = 128; st > 0; st >>= 1) {
        if (tid < st) sp[tid] += sp[tid + st];
        __syncthreads();
    }
    if (tid == 0) {
        double commit = 0.25 * sp[0] / (double)BD;
        out[BD + B] = (float)commit;
    }
}

extern "C" void kernel_launch(void* const* d_in, const int* in_sizes, int n_in,
                              void* d_out, int out_size) {
    const float* z = (const float*)d_in[0];
    const float* embed = (const float*)d_in[1];
    float* out = (float*)d_out;

    int B = in_sizes[0] / D_DIM;
    long BD = (long)B * D_DIM;
    int nblk = B / TM;
    int write_codes = ((long)out_size >= BD + B) ? 1 : 0;
    int write_commit = ((long)out_size >= BD + B + 1) ? 1 : 0;

    k_rowsq_xla<<<(K_CODES + 1) / 2, 256>>>(embed, K_CODES, /*dest=*/0);
    k_rowsq_xla<<<(B + 1) / 2, 256>>>(z, B, /*dest=*/1);
    k_main<<<nblk, NTHREADS>>>(z, embed, out, B, write_codes);
    if (write_commit)
        k_fin<<<1, 256>>>(out, nblk, BD, (long)B);
}

// round 14
// speedup vs baseline: 1.2246x; 1.2246x over previous
#include <cuda_runtime.h>
#include <cuda_bf16.h>
#include <math_constants.h>

// VQ forward: z (B,256) f32, embed (512,256) f32.
// out = [ quantized (B*256) | codes (B, as float) | commit (1) ]  (float32)
//
// Numerics contract (validated R9, PASS):
//   dot:    single-accumulator fp32 fma chain, k ascending (per row,col)
//   z_sq/e_sq: XLA:GPU row-reduce (vec=2, 128 thr, shfl trees)
//   dist = (z_sq - (2.0f*dot)) + e_sq  (separately rounded)
//   argmin: strict <, ascending col, tie -> lower index
//   quantized = z + (q - z), separately rounded
//
// R13 = R9 inner loop (2 LDS.128 + 6 movs + 8 FFMA2 per k; movs fill FFMA2
// rt=2 gap cycles) + single-sync double-buffered staging (TKS=32):
// prefetch tile t+1 to regs after the sync, compute tile t, STS into buf^1.
// 64 syncs total (R9: 256 sync crossings), staging latency hidden.

#define D_DIM 256
#define K_CODES 512
#define TM 64
#define TN 64
#define TKS 32
#define NKT (D_DIM / TKS)          // 8
#define NCT (K_CODES / TN)         // 8
#define NTILES (NCT * NKT)         // 64
#define NTHREADS 256
#define B_MAX 262144

__device__ float g_esq[K_CODES];
__device__ float g_zsq[B_MAX];
__device__ float g_partials[8192];

// ---- f32x2 packed helpers (sm_10x) ----
__device__ __forceinline__ unsigned long long pk2(float lo, float hi) {
    unsigned long long r;
    asm("mov.b64 %0, {%1, %2};" : "=l"(r) : "f"(lo), "f"(hi));
    return r;
}
__device__ __forceinline__ void fma2(unsigned long long& d,
                                     unsigned long long a,
                                     unsigned long long b) {
    asm("fma.rn.f32x2 %0, %1, %2, %0;" : "+l"(d) : "l"(a), "l"(b));
}
__device__ __forceinline__ float2 upk2(unsigned long long v) {
    float2 f;
    asm("mov.b64 {%0, %1}, %2;" : "=f"(f.x), "=f"(f.y) : "l"(v));
    return f;
}

// XLA:GPU row-reduce replica for sum(x*x) over a 256-float row.
// dest==0 -> g_esq, dest==1 -> g_zsq (symbols touched in device code only)
__global__ void k_rowsq_xla(const float* __restrict__ x, int rows, int dest) {
    __shared__ float w[8];
    const unsigned full = 0xffffffffu;
    int grp = threadIdx.x >> 7;
    int t = threadIdx.x & 127;
    long row = (long)blockIdx.x * 2 + grp;

    float s = 0.f;
    if (row < rows) {
        const float2 v = *(const float2*)(x + row * D_DIM + 2 * t);
        s = __fadd_rn(__fmul_rn(v.x, v.x), __fmul_rn(v.y, v.y));
    }
    s = __fadd_rn(s, __shfl_down_sync(full, s, 16));
    s = __fadd_rn(s, __shfl_down_sync(full, s, 8));
    s = __fadd_rn(s, __shfl_down_sync(full, s, 4));
    s = __fadd_rn(s, __shfl_down_sync(full, s, 2));
    s = __fadd_rn(s, __shfl_down_sync(full, s, 1));
    if ((threadIdx.x & 31) == 0) w[threadIdx.x >> 5] = s;
    __syncthreads();
    if ((t >> 5) == 0) {
        int lane = t & 31;
        float v = (lane < 4) ? w[grp * 4 + lane] : 0.f;
        v = __fadd_rn(v, __shfl_down_sync(full, v, 16));
        v = __fadd_rn(v, __shfl_down_sync(full, v, 8));
        v = __fadd_rn(v, __shfl_down_sync(full, v, 4));
        v = __fadd_rn(v, __shfl_down_sync(full, v, 2));
        v = __fadd_rn(v, __shfl_down_sync(full, v, 1));
        if (lane == 0 && row < rows) {
            if (dest == 0) g_esq[row] = v;
            else           g_zsq[row] = v;
        }
    }
}

__global__ __launch_bounds__(NTHREADS)
void k_main(const float* __restrict__ z, const float* __restrict__ embed,
            float* __restrict__ out, int B, int write_codes) {
    __shared__ __align__(16) float Zs[2][TKS][TM];   // 16KB double-buffered Z
    __shared__ __align__(16) float Es[2][TKS][TN];   // 16KB double-buffered E
    __shared__ float sMin[TM][16];
    __shared__ int   sIdx[TM][16];
    __shared__ int   sCode[TM];
    __shared__ float sPart[NTHREADS];
    __shared__ float sZsq[TM];

    const int tid = threadIdx.x;
    const int tx = tid & 15;          // cols tx*4 .. tx*4+3
    const int ty = tid >> 4;          // rows ty*4 .. ty*4+3
    const long rowBase = (long)blockIdx.x * TM;

    if (tid < TM) sZsq[tid] = g_zsq[rowBase + tid];

    float rmin[4];
    int   ridx[4];
#pragma unroll
    for (int r = 0; r < 4; r++) { rmin[r] = CUDART_INF_F; ridx[r] = 0; }

    // staging map: idx = tid + 256*h (h=0,1): m = idx&63, kq = idx>>6 (0..7)
    const int m0 = tid & 63;
    const int kq0 = tid >> 6;         // 0..3 ; second half: kq0+4

    // ---- prefetch tile 0 (ct=0, kt=0) and store to buf 0 ----
    float4 pz[2], pe[2];
#pragma unroll
    for (int h = 0; h < 2; h++) {
        int kq = kq0 + 4 * h;
        pz[h] = *(const float4*)(z + (rowBase + m0) * D_DIM + kq * 4);
        pe[h] = *(const float4*)(embed + (long)m0 * D_DIM + kq * 4);
    }
#pragma unroll
    for (int h = 0; h < 2; h++) {
        int kq = kq0 + 4 * h;
        Zs[0][kq * 4 + 0][m0] = pz[h].x;
        Zs[0][kq * 4 + 1][m0] = pz[h].y;
        Zs[0][kq * 4 + 2][m0] = pz[h].z;
        Zs[0][kq * 4 + 3][m0] = pz[h].w;
        Es[0][kq * 4 + 0][m0] = pe[h].x;
        Es[0][kq * 4 + 1][m0] = pe[h].y;
        Es[0][kq * 4 + 2][m0] = pe[h].z;
        Es[0][kq * 4 + 3][m0] = pe[h].w;
    }

    unsigned long long acc[4][2];     // [row][colpair]
#pragma unroll
    for (int r = 0; r < 4; r++) { acc[r][0] = 0ull; acc[r][1] = 0ull; }

    int buf = 0;
    for (int t = 0; t < NTILES; t++) {
        __syncthreads();              // buf ready; buf^1 free for stores

        // ---- prefetch tile t+1 into registers ----
        if (t + 1 < NTILES) {
            int ct2 = (t + 1) >> 3;
            int kt2 = (t + 1) & (NKT - 1);
#pragma unroll
            for (int h = 0; h < 2; h++) {
                int kq = kq0 + 4 * h;
                pz[h] = *(const float4*)(z + (rowBase + m0) * D_DIM +
                                         kt2 * TKS + kq * 4);
                pe[h] = *(const float4*)(embed + (long)(ct2 * TN + m0) * D_DIM +
                                         kt2 * TKS + kq * 4);
            }
        }

        // ---- compute 32 k-steps from buf (R9 inner loop) ----
#pragma unroll
        for (int k = 0; k < TKS; k++) {
            float4 za = *(const float4*)&Zs[buf][k][ty * 4];
            float4 ea = *(const float4*)&Es[buf][k][tx * 4];
            unsigned long long b01 = pk2(ea.x, ea.y);
            unsigned long long b23 = pk2(ea.z, ea.w);
            unsigned long long a0 = pk2(za.x, za.x);
            unsigned long long a1 = pk2(za.y, za.y);
            unsigned long long a2 = pk2(za.z, za.z);
            unsigned long long a3 = pk2(za.w, za.w);
            fma2(acc[0][0], a0, b01); fma2(acc[0][1], a0, b23);
            fma2(acc[1][0], a1, b01); fma2(acc[1][1], a1, b23);
            fma2(acc[2][0], a2, b01); fma2(acc[2][1], a2, b23);
            fma2(acc[3][0], a3, b01); fma2(acc[3][1], a3, b23);
        }

        // ---- end of ct: dist + running argmin (cols ascending) ----
        if ((t & (NKT - 1)) == NKT - 1) {
            int ct = t >> 3;
            int cb = ct * TN + tx * 4;
            float e0 = g_esq[cb + 0];
            float e1 = g_esq[cb + 1];
            float e2 = g_esq[cb + 2];
            float e3 = g_esq[cb + 3];
#pragma unroll
            for (int r = 0; r < 4; r++) {
                float zs = sZsq[ty * 4 + r];
                float2 d01 = upk2(acc[r][0]);
                float2 d23 = upk2(acc[r][1]);
                float s0 = __fadd_rn(__fsub_rn(zs, __fmul_rn(2.0f, d01.x)), e0);
                float s1 = __fadd_rn(__fsub_rn(zs, __fmul_rn(2.0f, d01.y)), e1);
                float s2 = __fadd_rn(__fsub_rn(zs, __fmul_rn(2.0f, d23.x)), e2);
                float s3 = __fadd_rn(__fsub_rn(zs, __fmul_rn(2.0f, d23.y)), e3);
                if (s0 < rmin[r]) { rmin[r] = s0; ridx[r] = cb + 0; }
                if (s1 < rmin[r]) { rmin[r] = s1; ridx[r] = cb + 1; }
                if (s2 < rmin[r]) { rmin[r] = s2; ridx[r] = cb + 2; }
                if (s3 < rmin[r]) { rmin[r] = s3; ridx[r] = cb + 3; }
                acc[r][0] = 0ull; acc[r][1] = 0ull;
            }
        }

        // ---- store prefetched tile into buf^1 ----
        if (t + 1 < NTILES) {
            int nb = buf ^ 1;
#pragma unroll
            for (int h = 0; h < 2; h++) {
                int kq = kq0 + 4 * h;
                Zs[nb][kq * 4 + 0][m0] = pz[h].x;
                Zs[nb][kq * 4 + 1][m0] = pz[h].y;
                Zs[nb][kq * 4 + 2][m0] = pz[h].z;
                Zs[nb][kq * 4 + 3][m0] = pz[h].w;
                Es[nb][kq * 4 + 0][m0] = pe[h].x;
                Es[nb][kq * 4 + 1][m0] = pe[h].y;
                Es[nb][kq * 4 + 2][m0] = pe[h].z;
                Es[nb][kq * 4 + 3][m0] = pe[h].w;
            }
        }
        buf ^= 1;
    }

    // ---- cross-thread argmin reduce (lower index wins ties) ----
    __syncthreads();
#pragma unroll
    for (int r = 0; r < 4; r++) {
        sMin[ty * 4 + r][tx] = rmin[r];
        sIdx[ty * 4 + r][tx] = ridx[r];
    }
    __syncthreads();
    if (tid < TM) {
        float m = sMin[tid][0];
        int ix = sIdx[tid][0];
#pragma unroll
        for (int x = 1; x < 16; x++) {
            float v = sMin[tid][x];
            int i2 = sIdx[tid][x];
            if (v < m || (v == m && i2 < ix)) { m = v; ix = i2; }
        }
        sCode[tid] = ix;
        if (write_codes)
            out[(long)B * D_DIM + rowBase + tid] = (float)ix;
    }
    __syncthreads();

    // ---- epilogue: gather q, quantized = z + (q - z), commit partial ----
    float lsum = 0.f;
    const float4* z4 = (const float4*)z;
    const float4* e4 = (const float4*)embed;
    float4* o4 = (float4*)out;
#pragma unroll 4
    for (int i = tid; i < TM * (D_DIM / 4); i += NTHREADS) {
        int r = i >> 6;
        int c = i & 63;
        int code = sCode[r];
        float4 qv = __ldg(&e4[(long)code * (D_DIM / 4) + c]);
        float4 zv = z4[(rowBase + r) * (D_DIM / 4) + c];
        float dx = __fsub_rn(qv.x, zv.x);
        float dy = __fsub_rn(qv.y, zv.y);
        float dz = __fsub_rn(qv.z, zv.z);
        float dw = __fsub_rn(qv.w, zv.w);
        float4 ov;
        ov.x = __fadd_rn(zv.x, dx);
        ov.y = __fadd_rn(zv.y, dy);
        ov.z = __fadd_rn(zv.z, dz);
        ov.w = __fadd_rn(zv.w, dw);
        o4[(rowBase + r) * (D_DIM / 4) + c] = ov;
        lsum += dx * dx + dy * dy + dz * dz + dw * dw;
    }
    sPart[tid] = lsum;
    __syncthreads();
#pragma unroll
    for (int s = NTHREADS / 2; s > 0; s >>= 1) {
        if (tid < s) sPart[tid] += sPart[tid + s];
        __syncthreads();
    }
    if (tid == 0) g_partials[blockIdx.x] = sPart[0];
}

__global__ void k_fin(float* __restrict__ out, int nblk, long BD, long B) {
    __shared__ double sp[256];
    int tid = threadIdx.x;
    double s = 0.0;
    for (int i = tid; i < nblk; i += 256) s += (double)g_partials[i];
    sp[tid] = s;
    __syncthreads();
    for (int st = 128; st > 0; st >>= 1) {
        if (tid < st) sp[tid] += sp[tid + st];
        __syncthreads();
    }
    if (tid == 0) {
        double commit = 0.25 * sp[0] / (double)BD;
        out[BD + B] = (float)commit;
    }
}

extern "C" void kernel_launch(void* const* d_in, const int* in_sizes, int n_in,
                              void* d_out, int out_size) {
    const float* z = (const float*)d_in[0];
    const float* embed = (const float*)d_in[1];
    float* out = (float*)d_out;

    int B = in_sizes[0] / D_DIM;
    long BD = (long)B * D_DIM;
    int nblk = B / TM;
    int write_codes = ((long)out_size >= BD + B) ? 1 : 0;
    int write_commit = ((long)out_size >= BD + B + 1) ? 1 : 0;

    k_rowsq_xla<<<(K_CODES + 1) / 2, 256>>>(embed, K_CODES, /*dest=*/0);
    k_rowsq_xla<<<(B + 1) / 2, 256>>>(z, B, /*dest=*/1);
    k_main<<<nblk, NTHREADS>>>(z, embed, out, B, write_codes);
    if (write_commit)
        k_fin<<<1, 256>>>(out, nblk, BD, (long)B);
}